// round 1
// baseline (speedup 1.0000x reference)
#include <cuda_runtime.h>

#define NCOLS 32768
#define TPB   1024
#define F4PT  8            // float4 per thread (8*4 = 32 floats)
#define VPT   32
#define KSEL  32
#define EQCAP 1024

__device__ __forceinline__ unsigned fkey(float f) {
    unsigned u = __float_as_uint(f);
    return u ^ ((u >> 31) ? 0xFFFFFFFFu : 0x80000000u);   // monotonic: bigger float -> bigger key
}
__device__ __forceinline__ float keyf(unsigned k) {
    unsigned u = (k & 0x80000000u) ? (k ^ 0x80000000u) : ~k;
    return __uint_as_float(u);
}

__global__ void __launch_bounds__(TPB, 1)
topk_kernel(const float* __restrict__ x, float* __restrict__ out) {
    __shared__ unsigned hist[256];
    __shared__ unsigned sufx[256];
    __shared__ unsigned sh_prefix, sh_need, sh_bin;
    __shared__ unsigned eq_cnt;
    __shared__ int eq_idx[EQCAP];

    const int row = blockIdx.x;
    const int t = threadIdx.x;
    const float4* __restrict__ xin = (const float4*)(x + (size_t)row * NCOLS);
    float4* __restrict__ xo = (float4*)(out + (size_t)row * NCOLS);

    // ---- Load full row into registers (coalesced, streaming) ----
    float4 v[F4PT];
#pragma unroll
    for (int j = 0; j < F4PT; j++)
        v[j] = __ldcs(&xin[t + j * TPB]);

    if (t == 0) { sh_prefix = 0u; sh_need = KSEL; eq_cnt = 0u; }

    // ---- 4-pass radix select (MSB-first, 8 bits/pass) for the K-th largest key ----
#pragma unroll 1
    for (int p = 0; p < 4; p++) {
        const int shift = 24 - 8 * p;
        if (t < 256) hist[t] = 0u;
        __syncthreads();                       // also publishes sh_prefix / sh_need

        const unsigned prefix = sh_prefix;
        const unsigned needLocal = sh_need;
        const unsigned hiMask = (p == 0) ? 0u : (0xFFFFFFFFu << (shift + 8));

        const float* fv = (const float*)v;
#pragma unroll
        for (int i = 0; i < VPT; i++) {
            unsigned k = fkey(fv[i]);
            unsigned bin = ((k & hiMask) == prefix) ? ((k >> shift) & 255u) : 256u;
            unsigned mask = __match_any_sync(0xFFFFFFFFu, bin);
            int leader = __ffs(mask) - 1;
            if ((int)(t & 31) == leader && bin < 256u)
                atomicAdd(&hist[bin], (unsigned)__popc(mask));
        }
        __syncthreads();

        // inclusive suffix-sum over 256 bins (Hillis–Steele)
        if (t < 256) sufx[t] = hist[t];
        __syncthreads();
#pragma unroll
        for (int off = 1; off < 256; off <<= 1) {
            unsigned add = 0u;
            if (t < 256 && t + off < 256) add = sufx[t + off];
            __syncthreads();
            if (t < 256) sufx[t] += add;
            __syncthreads();
        }

        // pick the bin containing the needLocal-th largest among matching elems
        if (t < 256) {
            unsigned Sb = sufx[t];
            unsigned Snext = (t == 255) ? 0u : sufx[t + 1];
            if (Sb >= needLocal && Snext < needLocal) {
                sh_bin = (unsigned)t;
                sh_need = needLocal - Snext;   // strictly-above count removed
            }
        }
        __syncthreads();
        if (t == 0) sh_prefix |= (sh_bin << shift);
        // visibility handled by the hist-clear __syncthreads at top of next pass
    }
    __syncthreads();

    const unsigned T = sh_prefix;        // exact key of K-th largest
    const unsigned need_eq = sh_need;    // how many elements == T to keep (index order)

    // ---- Write phase: out = (key > T) ? relu(x) : 0 ; collect equals ----
#pragma unroll
    for (int j = 0; j < F4PT; j++) {
        float4 w = v[j];
        const int base = (t + j * TPB) * 4;
        float* wp = (float*)&w;
#pragma unroll
        for (int c = 0; c < 4; c++) {
            unsigned k = fkey(wp[c]);
            if (k == T) {
                unsigned pos = atomicAdd(&eq_cnt, 1u);
                if (pos < EQCAP) eq_idx[pos] = base + c;
            }
            wp[c] = (k > T) ? fmaxf(wp[c], 0.0f) : 0.0f;
        }
        __stcs(&xo[t + j * TPB], w);
    }
    __syncthreads();

    // ---- Equals fixup (ties broken by lowest index, matching jax.lax.top_k) ----
    const unsigned ec = eq_cnt;
    const float tv = fmaxf(keyf(T), 0.0f);
    if (ec == need_eq) {
        // common case: all equals are selected (ec == need_eq <= 32)
        if (t < (int)ec)
            out[(size_t)row * NCOLS + eq_idx[t]] = tv;
    } else {
        // rare tie case: take need_eq smallest indices
        if (t == 0) {
            int n = (ec < EQCAP) ? (int)ec : EQCAP;
            for (unsigned s = 0; s < need_eq; s++) {
                int best = 0x7FFFFFFF, bi = -1;
                for (int i = 0; i < n; i++) {
                    int idx = eq_idx[i];
                    if (idx >= 0 && idx < best) { best = idx; bi = i; }
                }
                if (bi >= 0) {
                    eq_idx[bi] = -1;
                    out[(size_t)row * NCOLS + best] = tv;
                }
            }
        }
    }
}

extern "C" void kernel_launch(void* const* d_in, const int* in_sizes, int n_in,
                              void* d_out, int out_size) {
    const float* x = (const float*)d_in[0];
    float* out = (float*)d_out;
    const int rows = in_sizes[0] / NCOLS;
    topk_kernel<<<rows, TPB>>>(x, out);
}

// round 2
// speedup vs baseline: 3.9560x; 3.9560x over previous
#include <cuda_runtime.h>

#define NCOLS 32768
#define TPB   512
#define F4PT  16            // float4 per thread (16*4 = 64 floats)
#define KSEL  32
#define SLOTS 14
#define EQCAP 64
#define FLOORV 2.0f
#define FBCAP (TPB * SLOTS)  // fallback eq list capacity (reuses slots)

__device__ __forceinline__ unsigned fkey(float f) {
    unsigned u = __float_as_uint(f);
    return u ^ ((u >> 31) ? 0xFFFFFFFFu : 0x80000000u);   // monotonic
}
__device__ __forceinline__ float keyf(unsigned k) {
    unsigned u = (k & 0x80000000u) ? (k ^ 0x80000000u) : ~k;
    return __uint_as_float(u);
}

__global__ void __launch_bounds__(TPB, 3)
topk_kernel(const float* __restrict__ x, float* __restrict__ out) {
    __shared__ int      slots[TPB * SLOTS];   // 28 KB: per-thread private candidate idx slots
    __shared__ unsigned hist[256];
    __shared__ unsigned scn[257];
    __shared__ int      flagS;
    __shared__ unsigned eq_cnt;
    __shared__ int      eq_idx[EQCAP];
    __shared__ unsigned eq_key[EQCAP];
    __shared__ unsigned sh_cut, sh_above;
    __shared__ unsigned sh_bin, sh_need, fb_eqc;

    const int row = blockIdx.x;
    const int t   = threadIdx.x;
    const float* __restrict__ xrow = x + (size_t)row * NCOLS;
    float* __restrict__ orow = out + (size_t)row * NCOLS;
    const float4* __restrict__ xin4 = (const float4*)xrow;
    float4* __restrict__ xo4 = (float4*)orow;

    if (t == 0) { flagS = 0; eq_cnt = 0; }
    if (t < 256) hist[t] = 0;

    // ================= PHASE 1: single streaming pass =================
    // read row, write zeros, capture candidate indices (x >= 2.0) into
    // private per-thread slots. No atomics, no shared traffic in common path.
    int cnt = 0;
    const int slotbase = t * SLOTS;
    const float4 z4 = make_float4(0.f, 0.f, 0.f, 0.f);
#pragma unroll
    for (int j = 0; j < F4PT; j++) {
        float4 v = __ldcs(&xin4[t + j * TPB]);
        __stcs(&xo4[t + j * TPB], z4);
        float m = fmaxf(fmaxf(v.x, v.y), fmaxf(v.z, v.w));
        if (m >= FLOORV) {                       // ~8.9% of threads per float4
            int base = (t + j * TPB) * 4;
            if (v.x >= FLOORV) { if (cnt < SLOTS) slots[slotbase + cnt] = base + 0; cnt++; }
            if (v.y >= FLOORV) { if (cnt < SLOTS) slots[slotbase + cnt] = base + 1; cnt++; }
            if (v.z >= FLOORV) { if (cnt < SLOTS) slots[slotbase + cnt] = base + 2; cnt++; }
            if (v.w >= FLOORV) { if (cnt < SLOTS) slots[slotbase + cnt] = base + 3; cnt++; }
        }
    }
    if (cnt > SLOTS) flagS = 1;                  // slot overflow -> exact fallback
    const int myn = (cnt < SLOTS) ? cnt : SLOTS;
    __syncthreads();                             // zeros + slots + hist-clear visible

    // ================= PHASE 2: histogram candidates =================
    // bin = top 16 bits of float bits (all candidates positive, so raw bits order)
    for (int i = 0; i < myn; i++) {
        int idx = slots[slotbase + i];
        unsigned u = __float_as_uint(xrow[idx]);             // L2 hit
        unsigned bin = (u >> 16) - 0x4000u;                  // u >= 0x40000000
        bin = (bin > 255u) ? 255u : bin;
        atomicAdd(&hist[bin], 1u);
    }
    __syncthreads();

    // suffix scan over 256 bins
    if (t < 256) scn[t] = hist[t];
    if (t == 0) scn[256] = 0;
    __syncthreads();
#pragma unroll
    for (int off = 1; off < 256; off <<= 1) {
        unsigned a = (t < 256 && t + off < 256) ? scn[t + off] : 0u;
        __syncthreads();
        if (t < 256) scn[t] += a;
        __syncthreads();
    }
    if (t < 256) {
        if (scn[t] >= KSEL && scn[t + 1] < KSEL) { sh_cut = (unsigned)t; sh_above = scn[t + 1]; }
    }
    if (t == 0 && scn[0] < KSEL) flagS = 1;      // too few candidates -> fallback
    __syncthreads();

    // ================= PHASE 3: fast-path writes =================
    if (!flagS) {
        const unsigned cut = sh_cut;
        for (int i = 0; i < myn; i++) {
            int idx = slots[slotbase + i];
            float f = xrow[idx];
            unsigned u = __float_as_uint(f);
            unsigned bin = (u >> 16) - 0x4000u;
            bin = (bin > 255u) ? 255u : bin;
            if (bin > cut) {
                orow[idx] = f;                   // strictly above cut bin: guaranteed winner (f > 0)
            } else if (bin == cut) {
                unsigned p = atomicAdd(&eq_cnt, 1u);
                if (p < EQCAP) { eq_idx[p] = idx; eq_key[p] = u; }
                else flagS = 1;                  // eq overflow -> fallback (direct writes stay valid)
            }
        }
    }
    __syncthreads();

    if (!flagS) {
        // exact selection inside the cut bin: (value desc, index asc)
        const unsigned m = eq_cnt;
        const unsigned need = KSEL - sh_above;
        if (t < (int)m) {
            unsigned u = eq_key[t];
            int idx = eq_idx[t];
            unsigned r = 0;
            for (unsigned j = 0; j < m; j++) {
                unsigned uj = eq_key[j];
                if (uj > u || (uj == u && eq_idx[j] < idx)) r++;
            }
            if (r < need) orow[idx] = __uint_as_float(u);   // positive, relu identity
        }
        return;
    }

    // ================= EXACT FALLBACK (never taken for bench input) =================
    // Full 4-pass radix-256 select over the row (re-read, L2-resident).
    unsigned prefix = 0, needv = KSEL;
#pragma unroll 1
    for (int p = 0; p < 4; p++) {
        const int shift = 24 - 8 * p;
        if (t < 256) hist[t] = 0;
        __syncthreads();
        const unsigned hiMask = (p == 0) ? 0u : (0xFFFFFFFFu << (shift + 8));
#pragma unroll 1
        for (int j = 0; j < F4PT; j++) {
            float4 v = xin4[t + j * TPB];
            const float* fv = (const float*)&v;
            for (int c = 0; c < 4; c++) {
                unsigned k = fkey(fv[c]);
                if ((k & hiMask) == prefix)
                    atomicAdd(&hist[(k >> shift) & 255u], 1u);
            }
        }
        __syncthreads();
        if (t < 256) scn[t] = hist[t];
        if (t == 0) scn[256] = 0;
        __syncthreads();
        for (int off = 1; off < 256; off <<= 1) {
            unsigned a = (t < 256 && t + off < 256) ? scn[t + off] : 0u;
            __syncthreads();
            if (t < 256) scn[t] += a;
            __syncthreads();
        }
        if (t < 256) {
            if (scn[t] >= needv && scn[t + 1] < needv) {
                sh_bin = (unsigned)t; sh_need = needv - scn[t + 1];
            }
        }
        __syncthreads();
        prefix |= sh_bin << shift;
        needv = sh_need;
        __syncthreads();
    }
    const unsigned T = prefix;
    const unsigned need_eq = needv;
    if (t == 0) fb_eqc = 0;
    __syncthreads();
#pragma unroll 1
    for (int j = 0; j < F4PT; j++) {
        float4 v = xin4[t + j * TPB];
        const float* fv = (const float*)&v;
        int base = (t + j * TPB) * 4;
        for (int c = 0; c < 4; c++) {
            unsigned k = fkey(fv[c]);
            if (k > T) {
                orow[base + c] = fmaxf(fv[c], 0.0f);
            } else if (k == T) {
                unsigned p = atomicAdd(&fb_eqc, 1u);
                if (p < FBCAP) slots[p] = base + c;
            }
        }
    }
    __syncthreads();
    if (t == 0) {
        const float tv = fmaxf(keyf(T), 0.0f);
        unsigned n = fb_eqc;
        if (n <= FBCAP) {
            int nn = (int)n;
            for (unsigned s = 0; s < need_eq; s++) {
                int best = 0x7FFFFFFF, bi = -1;
                for (int i = 0; i < nn; i++) {
                    int idx = slots[i];
                    if (idx >= 0 && idx < best) { best = idx; bi = i; }
                }
                if (bi >= 0) { slots[bi] = -1; orow[best] = tv; }
            }
        } else {
            // absurd tie count: ordered rescan, still exact
            unsigned w = 0;
            for (int idx = 0; idx < NCOLS && w < need_eq; idx++) {
                if (fkey(xrow[idx]) == T) { orow[idx] = tv; w++; }
            }
        }
    }
}

extern "C" void kernel_launch(void* const* d_in, const int* in_sizes, int n_in,
                              void* d_out, int out_size) {
    const float* x = (const float*)d_in[0];
    float* out = (float*)d_out;
    const int rows = in_sizes[0] / NCOLS;
    topk_kernel<<<rows, TPB>>>(x, out);
}

// round 3
// speedup vs baseline: 5.8764x; 1.4854x over previous
#include <cuda_runtime.h>

#define NCOLS 32768
#define TPB   512
#define F4PT  16            // float4 per thread (16*4 = 64 floats)
#define KSEL  32
#define SLOTS 14
#define EQCAP 64
#define FLOORV 2.0f
#define FBCAP (TPB * SLOTS)

__device__ __forceinline__ unsigned fkey(float f) {
    unsigned u = __float_as_uint(f);
    return u ^ ((u >> 31) ? 0xFFFFFFFFu : 0x80000000u);
}
__device__ __forceinline__ float keyf(unsigned k) {
    unsigned u = (k & 0x80000000u) ? (k ^ 0x80000000u) : ~k;
    return __uint_as_float(u);
}

__global__ void __launch_bounds__(TPB, 3)
topk_kernel(const float* __restrict__ x, float* __restrict__ out) {
    __shared__ int      slots[TPB * SLOTS];   // 28 KB, per-thread private: (bin<<16)|idx
    __shared__ unsigned hist[256];
    __shared__ unsigned scn[257];             // fallback only
    __shared__ int      flagS;
    __shared__ unsigned eq_cnt;
    __shared__ int      eq_idx[EQCAP];
    __shared__ unsigned eq_key[EQCAP];
    __shared__ unsigned sh_cut, sh_above;
    __shared__ unsigned sh_bin, sh_need, fb_eqc;

    const int row = blockIdx.x;
    const int t   = threadIdx.x;
    const float* __restrict__ xrow = x + (size_t)row * NCOLS;
    float* __restrict__ orow = out + (size_t)row * NCOLS;
    const float4* __restrict__ xin4 = (const float4*)xrow;
    float4* __restrict__ xo4 = (float4*)orow;

    if (t == 0) { flagS = 0; eq_cnt = 0u; }
    if (t < 256) hist[t] = 0u;
    __syncthreads();                                         // [bar 1]

    // ===== PHASE 1: single streaming pass + fused histogram =====
    int cnt = 0;
    const int slotbase = t * SLOTS;
    const float4 z4 = make_float4(0.f, 0.f, 0.f, 0.f);
#pragma unroll
    for (int j = 0; j < F4PT; j++) {
        float4 v = __ldcs(&xin4[t + j * TPB]);
        __stcs(&xo4[t + j * TPB], z4);
        float m = fmaxf(fmaxf(v.x, v.y), fmaxf(v.z, v.w));
        if (m >= FLOORV) {                                   // rare (~9% of threads/iter)
            const int base = (t + j * TPB) * 4;
            const float* fp = (const float*)&v;
#pragma unroll
            for (int c = 0; c < 4; c++) {
                float f = fp[c];
                if (f >= FLOORV) {
                    unsigned u = __float_as_uint(f);
                    unsigned bin = (u >> 16) - 0x4000u;      // positive floats: bits monotone
                    bin = (bin > 255u) ? 255u : bin;
                    atomicAdd(&hist[bin], 1u);
                    if (cnt < SLOTS) slots[slotbase + cnt] = (int)((bin << 16) | (unsigned)(base + c));
                    cnt++;
                }
            }
        }
    }
    if (cnt > SLOTS) flagS = 1;                              // overflow -> exact fallback
    const int myn = (cnt < SLOTS) ? cnt : SLOTS;
    __syncthreads();                                         // [bar 2]

    // ===== PHASE 2: warp-0 suffix scan over 256 bins (no block barriers) =====
    if (t < 32) {
        unsigned h[8], tot = 0u;
#pragma unroll
        for (int c = 0; c < 8; c++) { h[c] = hist[t * 8 + c]; tot += h[c]; }
        unsigned v = tot;
#pragma unroll
        for (int off = 1; off < 32; off <<= 1) {             // cross-lane inclusive suffix
            unsigned o = __shfl_down_sync(0xFFFFFFFFu, v, off);
            if (t + off < 32) v += o;
        }
        unsigned nxt = v - tot;                              // suffix over bins in lanes > t
#pragma unroll
        for (int c = 7; c >= 0; c--) {                       // intra-chunk, high bin -> low
            unsigned s = nxt + h[c];                         // sufx[8t+c]
            if (s >= KSEL && nxt < KSEL) { sh_cut = (unsigned)(t * 8 + c); sh_above = nxt; }
            nxt = s;
        }
        if (t == 0 && v < KSEL) flagS = 1;                   // too few candidates -> fallback
    }
    __syncthreads();                                         // [bar 3]

    // ===== PHASE 3: fast-path writes (winner/eq re-reads only, ~34/row) =====
    if (!flagS) {
        const unsigned cut = sh_cut;
        for (int i = 0; i < myn; i++) {
            const int s = slots[slotbase + i];
            const unsigned bin = (unsigned)s >> 16;
            const int idx = s & 0xFFFF;
            if (bin > cut) {
                orow[idx] = xrow[idx];                       // guaranteed winner, f > 0
            } else if (bin == cut) {
                unsigned p = atomicAdd(&eq_cnt, 1u);
                if (p < EQCAP) { eq_idx[p] = idx; eq_key[p] = __float_as_uint(xrow[idx]); }
                else flagS = 1;
            }
        }
    }
    __syncthreads();                                         // [bar 4]

    if (!flagS) {
        // exact selection inside the cut bin: (value desc, index asc)
        const unsigned m = eq_cnt;
        const unsigned need = KSEL - sh_above;
        if (t < (int)m) {
            unsigned u = eq_key[t];
            int idx = eq_idx[t];
            unsigned r = 0;
            for (unsigned j = 0; j < m; j++) {
                unsigned uj = eq_key[j];
                if (uj > u || (uj == u && eq_idx[j] < idx)) r++;
            }
            if (r < need) orow[idx] = __uint_as_float(u);
        }
        return;
    }

    // ===== EXACT FALLBACK (never taken for bench input) =====
    unsigned prefix = 0, needv = KSEL;
#pragma unroll 1
    for (int p = 0; p < 4; p++) {
        const int shift = 24 - 8 * p;
        if (t < 256) hist[t] = 0u;
        __syncthreads();
        const unsigned hiMask = (p == 0) ? 0u : (0xFFFFFFFFu << (shift + 8));
#pragma unroll 1
        for (int j = 0; j < F4PT; j++) {
            float4 v = xin4[t + j * TPB];
            const float* fv = (const float*)&v;
            for (int c = 0; c < 4; c++) {
                unsigned k = fkey(fv[c]);
                if ((k & hiMask) == prefix)
                    atomicAdd(&hist[(k >> shift) & 255u], 1u);
            }
        }
        __syncthreads();
        if (t < 256) scn[t] = hist[t];
        if (t == 0) scn[256] = 0u;
        __syncthreads();
        for (int off = 1; off < 256; off <<= 1) {
            unsigned a = (t < 256 && t + off < 256) ? scn[t + off] : 0u;
            __syncthreads();
            if (t < 256) scn[t] += a;
            __syncthreads();
        }
        if (t < 256) {
            if (scn[t] >= needv && scn[t + 1] < needv) {
                sh_bin = (unsigned)t; sh_need = needv - scn[t + 1];
            }
        }
        __syncthreads();
        prefix |= sh_bin << shift;
        needv = sh_need;
        __syncthreads();
    }
    const unsigned T = prefix;
    const unsigned need_eq = needv;
    if (t == 0) fb_eqc = 0u;
    __syncthreads();
#pragma unroll 1
    for (int j = 0; j < F4PT; j++) {
        float4 v = xin4[t + j * TPB];
        const float* fv = (const float*)&v;
        int base = (t + j * TPB) * 4;
        for (int c = 0; c < 4; c++) {
            unsigned k = fkey(fv[c]);
            if (k > T) {
                orow[base + c] = fmaxf(fv[c], 0.0f);
            } else if (k == T) {
                unsigned p = atomicAdd(&fb_eqc, 1u);
                if (p < FBCAP) slots[p] = base + c;
            }
        }
    }
    __syncthreads();
    if (t == 0) {
        const float tv = fmaxf(keyf(T), 0.0f);
        unsigned n = fb_eqc;
        if (n <= FBCAP) {
            int nn = (int)n;
            for (unsigned s = 0; s < need_eq; s++) {
                int best = 0x7FFFFFFF, bi = -1;
                for (int i = 0; i < nn; i++) {
                    int idx = slots[i];
                    if (idx >= 0 && idx < best) { best = idx; bi = i; }
                }
                if (bi >= 0) { slots[bi] = -1; orow[best] = tv; }
            }
        } else {
            unsigned w = 0;
            for (int idx = 0; idx < NCOLS && w < need_eq; idx++) {
                if (fkey(xrow[idx]) == T) { orow[idx] = tv; w++; }
            }
        }
    }
}

extern "C" void kernel_launch(void* const* d_in, const int* in_sizes, int n_in,
                              void* d_out, int out_size) {
    const float* x = (const float*)d_in[0];
    float* out = (float*)d_out;
    const int rows = in_sizes[0] / NCOLS;
    topk_kernel<<<rows, TPB>>>(x, out);
}

// round 4
// speedup vs baseline: 6.8166x; 1.1600x over previous
#include <cuda_runtime.h>

#define NCOLS 32768
#define TPB   512
#define F4PT  16            // float4 per thread (16*4 = 64 floats)
#define KSEL  32
#define SLOTS 10
#define EQCAP 64
#define FLOORV 2.0f
#define FBCAP (TPB * SLOTS)

__device__ __forceinline__ unsigned fkey(float f) {
    unsigned u = __float_as_uint(f);
    return u ^ ((u >> 31) ? 0xFFFFFFFFu : 0x80000000u);
}
__device__ __forceinline__ float keyf(unsigned k) {
    unsigned u = (k & 0x80000000u) ? (k ^ 0x80000000u) : ~k;
    return __uint_as_float(u);
}

__global__ void __launch_bounds__(TPB, 3)
topk_kernel(const float* __restrict__ x, float* __restrict__ out) {
    __shared__ int      slots[TPB * SLOTS];   // 20 KB: (bin<<16)|idx
    __shared__ float    svals[TPB * SLOTS];   // 20 KB: candidate values (no gmem re-read)
    __shared__ unsigned hist[256];
    __shared__ unsigned scn[257];             // fallback only
    __shared__ int      flagS;
    __shared__ unsigned eq_cnt;
    __shared__ int      eq_idx[EQCAP];
    __shared__ unsigned eq_key[EQCAP];
    __shared__ unsigned sh_cut, sh_above;
    __shared__ unsigned sh_bin, sh_need, fb_eqc;

    const int row = blockIdx.x;
    const int t   = threadIdx.x;
    const float* __restrict__ xrow = x + (size_t)row * NCOLS;
    float* __restrict__ orow = out + (size_t)row * NCOLS;
    const float4* __restrict__ xin4 = (const float4*)xrow;
    float4* __restrict__ xo4 = (float4*)orow;

    if (t == 0) { flagS = 0; eq_cnt = 0u; }
    if (t < 256) hist[t] = 0u;
    __syncthreads();                                         // [bar 1]

    // ===== PHASE 1: streaming pass, 4-deep load batches, fused histogram =====
    int cnt = 0;
    const int slotbase = t * SLOTS;
    const float4 z4 = make_float4(0.f, 0.f, 0.f, 0.f);
#pragma unroll
    for (int jb = 0; jb < F4PT / 4; jb++) {
        float4 v[4];
#pragma unroll
        for (int u = 0; u < 4; u++)                           // 4 back-to-back LDG.128
            v[u] = __ldcs(&xin4[t + (jb * 4 + u) * TPB]);
#pragma unroll
        for (int u = 0; u < 4; u++)                           // 4 back-to-back STG.128
            __stcs(&xo4[t + (jb * 4 + u) * TPB], z4);
#pragma unroll
        for (int u = 0; u < 4; u++) {
            float m = fmaxf(fmaxf(v[u].x, v[u].y), fmaxf(v[u].z, v[u].w));
            if (m >= FLOORV) {                                // rare
                const int base = (t + (jb * 4 + u) * TPB) * 4;
                const float* fp = (const float*)&v[u];
#pragma unroll
                for (int c = 0; c < 4; c++) {
                    float f = fp[c];
                    if (f >= FLOORV) {
                        unsigned ub = __float_as_uint(f);
                        unsigned bin = (ub >> 16) - 0x4000u;
                        bin = (bin > 255u) ? 255u : bin;
                        atomicAdd(&hist[bin], 1u);
                        if (cnt < SLOTS) {
                            slots[slotbase + cnt] = (int)((bin << 16) | (unsigned)(base + c));
                            svals[slotbase + cnt] = f;
                        }
                        cnt++;
                    }
                }
            }
        }
    }
    if (cnt > SLOTS) flagS = 1;
    const int myn = (cnt < SLOTS) ? cnt : SLOTS;
    __syncthreads();                                         // [bar 2]

    // ===== PHASE 2: warp-0 suffix scan over 256 bins =====
    if (t < 32) {
        unsigned h[8], tot = 0u;
#pragma unroll
        for (int c = 0; c < 8; c++) { h[c] = hist[t * 8 + c]; tot += h[c]; }
        unsigned v = tot;
#pragma unroll
        for (int off = 1; off < 32; off <<= 1) {
            unsigned o = __shfl_down_sync(0xFFFFFFFFu, v, off);
            if (t + off < 32) v += o;
        }
        unsigned nxt = v - tot;
#pragma unroll
        for (int c = 7; c >= 0; c--) {
            unsigned s = nxt + h[c];
            if (s >= KSEL && nxt < KSEL) { sh_cut = (unsigned)(t * 8 + c); sh_above = nxt; }
            nxt = s;
        }
        if (t == 0 && v < KSEL) flagS = 1;
    }
    __syncthreads();                                         // [bar 3]

    // ===== PHASE 3: fast-path writes — values from shared, no gmem reads =====
    if (!flagS) {
        const unsigned cut = sh_cut;
        for (int i = 0; i < myn; i++) {
            const int s = slots[slotbase + i];
            const unsigned bin = (unsigned)s >> 16;
            const int idx = s & 0xFFFF;
            const float f = svals[slotbase + i];
            if (bin > cut) {
                orow[idx] = f;                                // winner, f > 0 (relu identity)
            } else if (bin == cut) {
                unsigned p = atomicAdd(&eq_cnt, 1u);
                if (p < EQCAP) { eq_idx[p] = idx; eq_key[p] = __float_as_uint(f); }
                else flagS = 1;
            }
        }
    }
    __syncthreads();                                         // [bar 4]

    if (!flagS) {
        // exact rank inside the cut bin: (value desc, index asc)
        const unsigned m = eq_cnt;
        const unsigned need = KSEL - sh_above;
        if (t < (int)m) {
            unsigned u = eq_key[t];
            int idx = eq_idx[t];
            unsigned r = 0;
            for (unsigned j = 0; j < m; j++) {
                unsigned uj = eq_key[j];
                if (uj > u || (uj == u && eq_idx[j] < idx)) r++;
            }
            if (r < need) orow[idx] = __uint_as_float(u);
        }
        return;
    }

    // ===== EXACT FALLBACK (never taken for bench input) =====
    unsigned prefix = 0, needv = KSEL;
#pragma unroll 1
    for (int p = 0; p < 4; p++) {
        const int shift = 24 - 8 * p;
        if (t < 256) hist[t] = 0u;
        __syncthreads();
        const unsigned hiMask = (p == 0) ? 0u : (0xFFFFFFFFu << (shift + 8));
#pragma unroll 1
        for (int j = 0; j < F4PT; j++) {
            float4 v = xin4[t + j * TPB];
            const float* fv = (const float*)&v;
            for (int c = 0; c < 4; c++) {
                unsigned k = fkey(fv[c]);
                if ((k & hiMask) == prefix)
                    atomicAdd(&hist[(k >> shift) & 255u], 1u);
            }
        }
        __syncthreads();
        if (t < 256) scn[t] = hist[t];
        if (t == 0) scn[256] = 0u;
        __syncthreads();
        for (int off = 1; off < 256; off <<= 1) {
            unsigned a = (t < 256 && t + off < 256) ? scn[t + off] : 0u;
            __syncthreads();
            if (t < 256) scn[t] += a;
            __syncthreads();
        }
        if (t < 256) {
            if (scn[t] >= needv && scn[t + 1] < needv) {
                sh_bin = (unsigned)t; sh_need = needv - scn[t + 1];
            }
        }
        __syncthreads();
        prefix |= sh_bin << shift;
        needv = sh_need;
        __syncthreads();
    }
    const unsigned T = prefix;
    const unsigned need_eq = needv;
    if (t == 0) fb_eqc = 0u;
    __syncthreads();
#pragma unroll 1
    for (int j = 0; j < F4PT; j++) {
        float4 v = xin4[t + j * TPB];
        const float* fv = (const float*)&v;
        int base = (t + j * TPB) * 4;
        for (int c = 0; c < 4; c++) {
            unsigned k = fkey(fv[c]);
            if (k > T) {
                orow[base + c] = fmaxf(fv[c], 0.0f);
            } else if (k == T) {
                unsigned p = atomicAdd(&fb_eqc, 1u);
                if (p < FBCAP) slots[p] = base + c;
            }
        }
    }
    __syncthreads();
    if (t == 0) {
        const float tv = fmaxf(keyf(T), 0.0f);
        unsigned n = fb_eqc;
        if (n <= FBCAP) {
            int nn = (int)n;
            for (unsigned s = 0; s < need_eq; s++) {
                int best = 0x7FFFFFFF, bi = -1;
                for (int i = 0; i < nn; i++) {
                    int idx = slots[i];
                    if (idx >= 0 && idx < best) { best = idx; bi = i; }
                }
                if (bi >= 0) { slots[bi] = -1; orow[best] = tv; }
            }
        } else {
            unsigned w = 0;
            for (int idx = 0; idx < NCOLS && w < need_eq; idx++) {
                if (fkey(xrow[idx]) == T) { orow[idx] = tv; w++; }
            }
        }
    }
}

extern "C" void kernel_launch(void* const* d_in, const int* in_sizes, int n_in,
                              void* d_out, int out_size) {
    const float* x = (const float*)d_in[0];
    float* out = (float*)d_out;
    const int rows = in_sizes[0] / NCOLS;
    topk_kernel<<<rows, TPB>>>(x, out);
}